// round 9
// baseline (speedup 1.0000x reference)
#include <cuda_runtime.h>
#include <cstdint>

// ExtractTensorPatches: x (4,32,256,256) f32 -> out (4,961,32,16,16) f32
// out[b,l,c,i,j] = x[b,c,oh*8+i,ow*8+j] + EPS * patch_sum(b,c,oh,ow)
// l = oh*31 + ow.
//
// One CTA per (b,c,oh): loads 16x256 input row band into smem once,
// computes all 31 patch sums, streams out 31 patches with 256-bit
// (v8.b32) streaming stores: one warp writes one full 1KB patch per step.

#define CHAN   32
#define HW     256
#define WIN    16
#define STR    8
#define HO     31
#define WO     31
#define LPATCH (HO * WO)       // 961
#define TPAD   272             // 256 + 16 pad

__device__ __forceinline__ float4 ld4g(const float* p) {
    return *reinterpret_cast<const float4*>(p);
}

__device__ __forceinline__ void st8_cs(float* p, float4 a, float4 b) {
    asm volatile("st.global.cs.v8.b32 [%0], {%1,%2,%3,%4,%5,%6,%7,%8};"
                 :: "l"(p),
                    "f"(a.x), "f"(a.y), "f"(a.z), "f"(a.w),
                    "f"(b.x), "f"(b.y), "f"(b.z), "f"(b.w)
                 : "memory");
}

__global__ __launch_bounds__(256)
void extract_patches_kernel(const float* __restrict__ x, float* __restrict__ out) {
    const float EPS = 1e-6f;

    __shared__ float tile[WIN][TPAD];     // 16 rows x 256 (+16 pad) floats
    __shared__ float part[64][5];         // per-(col4, row-group) partials
    __shared__ float colsum4[64];         // sum over 16 rows of each 4-col group
    __shared__ float psum[WO + 1];        // 31 patch sums

    int bx = blockIdx.x;
    int oh = bx % HO;
    int c  = (bx / HO) & (CHAN - 1);
    int b  = bx / (HO * CHAN);

    int tid  = threadIdx.x;
    int wid  = tid >> 5;
    int lane = tid & 31;

    const float* src = x + ((size_t)(b * CHAN + c) * HW + (size_t)(oh * STR)) * HW;

    // ---- Phase 1: load 16x256 band (1024 float4s; 4 per thread), accumulate
    // per-thread partial sum. Thread: col4 = tid&63, rows r0+{0,4,8,12}.
    int col4 = tid & 63;
    int r0   = tid >> 6;
    float acc = 0.f;
    #pragma unroll
    for (int k = 0; k < 4; k++) {
        int r = r0 + 4 * k;
        float4 v = ld4g(src + (size_t)r * HW + col4 * 4);
        acc += v.x + v.y + v.z + v.w;
        *reinterpret_cast<float4*>(&tile[r][col4 * 4]) = v;
    }
    part[col4][r0] = acc;
    __syncthreads();

    // ---- Phase 2: column-group sums over all 16 rows (threads 0..63)
    if (tid < 64) {
        colsum4[tid] = part[tid][0] + part[tid][1] + part[tid][2] + part[tid][3];
    }
    __syncthreads();

    // ---- Phase 3: patch sums (threads 0..30)
    if (tid < WO) {
        int g0 = 2 * tid;
        psum[tid] = colsum4[g0] + colsum4[g0 + 1] + colsum4[g0 + 2] + colsum4[g0 + 3];
    }
    __syncthreads();

    // ---- Phase 4: 31 patch tasks over 8 warps; one warp = one full 1KB patch.
    // lane -> float8 q8: row i = lane>>1, 32B half s = lane&1.
    size_t out_base = (((size_t)b * LPATCH + (size_t)oh * WO) * CHAN + c) * (size_t)(WIN * WIN);
    int i = lane >> 1;
    int s = lane & 1;
    #pragma unroll
    for (int p = wid; p < WO; p += 8) {
        const float* srow = &tile[i][p * STR + s * 8];
        float4 a = *reinterpret_cast<const float4*>(srow);
        float4 bb = *reinterpret_cast<const float4*>(srow + 4);
        float e = EPS * psum[p];
        a.x += e; a.y += e; a.z += e; a.w += e;
        bb.x += e; bb.y += e; bb.z += e; bb.w += e;

        float* dst = out + out_base + (size_t)p * (CHAN * WIN * WIN) + lane * 8;
        st8_cs(dst, a, bb);
    }
}

extern "C" void kernel_launch(void* const* d_in, const int* in_sizes, int n_in,
                              void* d_out, int out_size) {
    const float* x = (const float*)d_in[0];
    float* out = (float*)d_out;

    dim3 grid(4 * CHAN * HO);   // 3968 CTAs: one per (b, c, oh)
    dim3 block(256);
    extract_patches_kernel<<<grid, block>>>(x, out);
}

// round 10
// speedup vs baseline: 1.0089x; 1.0089x over previous
#include <cuda_runtime.h>

// ExtractTensorPatches: x (4,32,256,256) f32 -> out (4,961,32,16,16) f32
// out[b,l,c,i,j] = x[b,c,oh*8+i,ow*8+j] + EPS * patch_sum(b,c,oh,ow)
// l = oh*31 + ow.
//
// One CTA per (b,l): handles all 32 channels of one patch and writes one
// CONTIGUOUS 32KB output block (maximal DRAM write bursts). 8 threads per
// channel; patch data lives in registers; patch sum via 8-lane shuffle
// reduction. No shared memory, no __syncthreads.

#define CHAN   32
#define HW     256
#define STR    8
#define HO     31
#define WO     31
#define LPATCH (HO * WO)       // 961

__device__ __forceinline__ float4 ld4g(const float* p) {
    return *reinterpret_cast<const float4*>(p);
}

__global__ __launch_bounds__(256)
void extract_patches_kernel(const float* __restrict__ x, float* __restrict__ out) {
    const float EPS = 1e-6f;

    int bx = blockIdx.x;
    int l  = bx % LPATCH;
    int b  = bx / LPATCH;
    int oh = l / WO;
    int ow = l % WO;

    int tid = threadIdx.x;
    int c   = tid >> 3;        // channel 0..31
    int j   = tid & 7;         // lane-in-channel 0..7

    const float* src = x + ((size_t)(b * CHAN + c) * HW + (size_t)(oh * STR)) * HW
                         + (size_t)(ow * STR);

    // Each thread loads 8 float4s of its channel's 16x16 patch:
    // float4 index idx = j + 8k (k=0..7); row = idx>>2, seg = idx&3.
    float4 v[8];
    float acc = 0.f;
    #pragma unroll
    for (int k = 0; k < 8; k++) {
        int idx = j + 8 * k;
        int row = idx >> 2;
        int seg = idx & 3;
        v[k] = ld4g(src + (size_t)row * HW + seg * 4);
        acc += v[k].x + v[k].y + v[k].z + v[k].w;
    }

    // 8-lane reduction within the channel group (lanes g*8..g*8+7 of the warp).
    #pragma unroll
    for (int m = 1; m < 8; m <<= 1)
        acc += __shfl_xor_sync(0xffffffffu, acc, m);
    float e = EPS * acc;

    // Store: CTA writes out[b,l,:,:,:] = 32KB contiguous; thread's float4s at
    // c*256 + idx*4 floats. Warp-level: 4 chunks of 128B -> dense bursts.
    float* dst = out + (((size_t)b * LPATCH + l) * CHAN + c) * 256;
    #pragma unroll
    for (int k = 0; k < 8; k++) {
        int idx = j + 8 * k;
        float4 o = v[k];
        o.x += e; o.y += e; o.z += e; o.w += e;
        __stcs(reinterpret_cast<float4*>(dst + idx * 4), o);
    }
}

extern "C" void kernel_launch(void* const* d_in, const int* in_sizes, int n_in,
                              void* d_out, int out_size) {
    const float* x = (const float*)d_in[0];
    float* out = (float*)d_out;

    dim3 grid(4 * LPATCH);   // 3844 CTAs: one per (b, l)
    dim3 block(256);
    extract_patches_kernel<<<grid, block>>>(x, out);
}

// round 11
// speedup vs baseline: 1.0756x; 1.0661x over previous
#include <cuda_runtime.h>

// ExtractTensorPatches: x (4,32,256,256) f32 -> out (4,961,32,16,16) f32
// out[b,l,c,i,j] = x[b,c,oh*8+i,ow*8+j] + EPS * patch_sum(b,c,oh,ow)
// l = oh*31 + ow.
//
// Persistent CTAs (148*6), each looping over (b,c,oh) tiles with a
// DOUBLE-BUFFERED input tile: phase-1 loads of tile n+1 overlap the store
// drain of tile n (no end-of-loop __syncthreads on the big buffer).

#define CHAN   32
#define HW     256
#define WIN    16
#define STR    8
#define HO     31
#define WO     31
#define LPATCH (HO * WO)       // 961
#define NTILES (4 * CHAN * HO) // 3968
#define TPAD   272             // rows i/i+1 hit disjoint bank halves

__device__ __forceinline__ float4 ld4g(const float* p) {
    return *reinterpret_cast<const float4*>(p);
}

__global__ __launch_bounds__(256)
void extract_patches_kernel(const float* __restrict__ x, float* __restrict__ out) {
    const float EPS = 1e-6f;

    __shared__ float tile[2][WIN][TPAD];  // double-buffered 16x256 band
    __shared__ float part[64][5];
    __shared__ float colsum4[64];
    __shared__ float psum[WO + 1];

    int tid  = threadIdx.x;
    int wid  = tid >> 5;
    int lane = tid & 31;
    int col4 = tid & 63;
    int r0   = tid >> 6;

    int buf = 0;
    for (int t = blockIdx.x; t < NTILES; t += gridDim.x, buf ^= 1) {
        int oh = t % HO;
        int c  = (t / HO) & (CHAN - 1);
        int b  = t / (HO * CHAN);

        const float* src = x + ((size_t)(b * CHAN + c) * HW + (size_t)(oh * STR)) * HW;

        // ---- Phase 1: load 16x256 band into tile[buf] (4 float4/thread),
        // accumulate per-thread partial. Overlaps prior tile's store drain.
        float acc = 0.f;
        #pragma unroll
        for (int k = 0; k < 4; k++) {
            int r = r0 + 4 * k;
            float4 v = ld4g(src + (size_t)r * HW + col4 * 4);
            acc += v.x + v.y + v.z + v.w;
            *reinterpret_cast<float4*>(&tile[buf][r][col4 * 4]) = v;
        }
        __syncthreads();               // prior iter's psum reads done; part safe
        part[col4][r0] = acc;
        __syncthreads();

        // ---- Phase 2: column-group sums over 16 rows (threads 0..63)
        if (tid < 64) {
            colsum4[tid] = part[tid][0] + part[tid][1] + part[tid][2] + part[tid][3];
        }
        __syncthreads();

        // ---- Phase 3: patch sums (threads 0..30)
        if (tid < WO) {
            int g0 = 2 * tid;
            psum[tid] = colsum4[g0] + colsum4[g0 + 1] + colsum4[g0 + 2] + colsum4[g0 + 3];
        }
        __syncthreads();

        // ---- Phase 4: 62 half-patch tasks over 8 warps; streaming stores.
        // No trailing sync: next iteration loads into the other buffer.
        size_t out_base = (((size_t)b * LPATCH + (size_t)oh * WO) * CHAN + c)
                          * (size_t)(WIN * WIN);
        #pragma unroll
        for (int tt = wid; tt < 62; tt += 8) {
            int p = tt >> 1;
            int h = tt & 1;
            int q = lane + 32 * h;
            int i = q >> 2;
            int s = q & 3;

            float4 v = *reinterpret_cast<const float4*>(&tile[buf][i][p * STR + s * 4]);
            float e = EPS * psum[p];
            v.x += e; v.y += e; v.z += e; v.w += e;

            float* dst = out + out_base + (size_t)p * (CHAN * WIN * WIN) + q * 4;
            __stcs(reinterpret_cast<float4*>(dst), v);
        }
    }
}

extern "C" void kernel_launch(void* const* d_in, const int* in_sizes, int n_in,
                              void* d_out, int out_size) {
    const float* x = (const float*)d_in[0];
    float* out = (float*)d_out;

    dim3 grid(148 * 6);   // persistent: ~6 CTAs/SM, one wave
    dim3 block(256);
    extract_patches_kernel<<<grid, block>>>(x, out);
}